// round 5
// baseline (speedup 1.0000x reference)
#include <cuda_runtime.h>
#include <cuda_bf16.h>
#include <math.h>
#include <stdint.h>

// ---------------- problem constants ----------------
#define Bc   2
#define Tc   2048
#define Dc   1024
#define Hc   16
#define HDc  64
#define DFFc 4096
#define Lc   8
#define Vc   50257
#define BTc  (Bc*Tc)          // 4096
#define EPSc 1e-5f

// ---------------- static device scratch (no allocs allowed) ----------------
__device__ float g_h  [BTc*Dc];
__device__ float g_xn [BTc*Dc];
__device__ float g_q  [BTc*Dc];
__device__ float g_k  [BTc*Dc];
__device__ float g_v  [BTc*Dc];
__device__ float g_ctx[BTc*Dc];
__device__ float g_ff [(long)BTc*DFFc];
__device__ float g_sc [(long)Bc*Hc*Tc*Tc];   // scores / probs (in-place softmax)
__device__ float g_fin[Bc*Dc];               // final-LN of last tokens

// ---------------- helpers ----------------
__device__ __forceinline__ float gelu_f(float x) {
    const float c = 0.7978845608028654f;
    return 0.5f * x * (1.0f + tanhf(c * (x + 0.044715f * x * x * x)));
}
__device__ __forceinline__ float tf32r(float x) {
    uint32_t u;
    asm("cvt.rna.tf32.f32 %0, %1;" : "=r"(u) : "f"(x));
    return __uint_as_float(u);
}
__device__ __forceinline__ void mma_tf32(float* c, const uint32_t* a, const uint32_t* b) {
    asm volatile(
        "mma.sync.aligned.m16n8k8.row.col.f32.tf32.tf32.f32 "
        "{%0,%1,%2,%3}, {%4,%5,%6,%7}, {%8,%9}, {%0,%1,%2,%3};"
        : "+f"(c[0]), "+f"(c[1]), "+f"(c[2]), "+f"(c[3])
        : "r"(a[0]), "r"(a[1]), "r"(a[2]), "r"(a[3]), "r"(b[0]), "r"(b[1]));
}

// ---------------- embedding ----------------
__global__ void embed_k(const int* __restrict__ x,
                        const float* __restrict__ Wemb,
                        const float* __restrict__ pos,
                        float* __restrict__ h)
{
    long i = (long)blockIdx.x * blockDim.x + threadIdx.x;
    if (i >= (long)BTc * Dc) return;
    int row = (int)(i / Dc);
    int d   = (int)(i % Dc);
    int t   = row % Tc;
    int tok = x[row];
    h[i] = Wemb[(long)tok * Dc + d] + pos[(long)t * Dc + d];
}

// ---------------- layernorm (ddof=1, std+eps) ----------------
__global__ void ln_k(const float* __restrict__ in, long inStride,
                     float* __restrict__ out, long outStride,
                     const float* __restrict__ sc, const float* __restrict__ sh)
{
    __shared__ float red[256];
    int r = blockIdx.x, tid = threadIdx.x;
    const float* x = in + (long)r * inStride;
    float xv[4];
    float s = 0.f;
#pragma unroll
    for (int i = 0; i < 4; i++) { xv[i] = x[tid + i * 256]; s += xv[i]; }
    red[tid] = s; __syncthreads();
    for (int st = 128; st > 0; st >>= 1) { if (tid < st) red[tid] += red[tid + st]; __syncthreads(); }
    float mean = red[0] * (1.0f / (float)Dc);
    __syncthreads();
    float v = 0.f;
#pragma unroll
    for (int i = 0; i < 4; i++) { float t = xv[i] - mean; v += t * t; }
    red[tid] = v; __syncthreads();
    for (int st = 128; st > 0; st >>= 1) { if (tid < st) red[tid] += red[tid + st]; __syncthreads(); }
    float inv = 1.0f / (sqrtf(red[0] / (float)(Dc - 1)) + EPSc);
    float* o = out + (long)r * outStride;
#pragma unroll
    for (int i = 0; i < 4; i++) { int d = tid + i * 256; o[d] = sc[d] * ((xv[i] - mean) * inv) + sh[d]; }
}

// ---------------- causal softmax ----------------
__global__ void softmax_k(float* __restrict__ S)
{
    long row = blockIdx.x;                 // = z*T + q
    int  q   = (int)(row % Tc);
    float* p = S + row * (long)Tc;
    int len  = q + 1;
    int tid  = threadIdx.x;
    __shared__ float red[256];

    float mx = -1e30f;
    for (int k = tid; k < len; k += 256) mx = fmaxf(mx, p[k]);
    red[tid] = mx; __syncthreads();
    for (int st = 128; st > 0; st >>= 1) { if (tid < st) red[tid] = fmaxf(red[tid], red[tid + st]); __syncthreads(); }
    mx = red[0]; __syncthreads();

    float sum = 0.f;
    for (int k = tid; k < len; k += 256) sum += expf(p[k] - mx);
    red[tid] = sum; __syncthreads();
    for (int st = 128; st > 0; st >>= 1) { if (tid < st) red[tid] += red[tid + st]; __syncthreads(); }
    float inv = 1.0f / red[0];

    for (int k = tid; k < len; k += 256) p[k] = expf(p[k] - mx) * inv;
    int kzend = ((q >> 7) + 1) << 7; if (kzend > Tc) kzend = Tc;
    for (int k = len + tid; k < kzend; k += 256) p[k] = 0.f;
}

// =====================================================================
// gemm_nt2: NT GEMM, 128x128 block, 4 warps of 64x64 tiles, 128 threads.
// Requires: M,N multiples of 128, K multiple of 16, 16B-aligned rows.
// C = scale*(A[M,K] @ B[N,K]^T) [+bias][gelu][+resid]
// Fragment-slot smem layout: one float4 per consumer LDS.128.
//   sA slot[ks][j][c][g] = {A[16j+g][8ks+c], A[16j+8+g][8ks+c],
//                           A[16j+g][8ks+c+4], A[16j+8+g][8ks+c+4]}
//   sB slot[ks][j][c][g] = {B[16j+g][8ks+c], B[16j+g][8ks+c+4],
//                           B[16j+8+g][8ks+c], B[16j+8+g][8ks+c+4]}
// =====================================================================
#define NBK 16

__global__ __launch_bounds__(128, 2)
void gemm_nt2(const float* __restrict__ A, int lda, long aO1, long aO2,
              const float* __restrict__ B, int ldb, long bO1, long bO2,
              float* __restrict__ C, int ldc, long cO1, long cO2,
              int K,
              const float* __restrict__ bias,
              const float* __restrict__ resid,
              float scale, int doGelu, int causalSkip, int Hdiv)
{
    int m0 = blockIdx.y * 128;
    int n0 = blockIdx.x * 128;
    if (causalSkip && n0 > m0 + 127) return;

    int z  = blockIdx.z;
    int zb = z / Hdiv, zh = z % Hdiv;
    A += (long)zb * aO1 + (long)zh * aO2;
    B += (long)zb * bO1 + (long)zh * bO2;
    C += (long)zb * cO1 + (long)zh * cO2;
    const float* R = resid ? (resid + (long)zb * cO1 + (long)zh * cO2) : (const float*)0;

    __shared__ float4 sA[2][512];
    __shared__ float4 sB[2][512];

    int tid  = threadIdx.x;
    int lane = tid & 31, warp = tid >> 5;
    int wm = (warp & 1) * 64, wn = (warp >> 1) * 64;
    int jA = wm >> 4, jB = wn >> 4;
    int g  = lane >> 2, c = lane & 3;

    float acc[4][8][4];
#pragma unroll
    for (int i = 0; i < 4; i++)
#pragma unroll
        for (int j = 0; j < 8; j++)
#pragma unroll
            for (int e = 0; e < 4; e++) acc[i][j][e] = 0.f;

    // ---- staging role: thread covers rows r0, r0+8 over 8 k, for A and B ----
    int ks = tid >> 6;            // k-half 0/1
    int pr = tid & 63;
    int js = pr >> 3, gs = pr & 7;
    int r0 = js * 16 + gs;
    const float* Ap = A + (long)(m0 + r0) * lda + ks * 8;
    const float* Bp = B + (long)(n0 + r0) * ldb + ks * 8;
    int sbase = ks * 256 + js * 32 + gs;   // + c'*8

    int nIter = K / NBK;

    float4 va0, va1, va2, va3, vb0, vb1, vb2, vb3;
    // prologue: load + stage chunk 0
    va0 = *(const float4*)(Ap);                 va1 = *(const float4*)(Ap + 4);
    va2 = *(const float4*)(Ap + 8L * lda);      va3 = *(const float4*)(Ap + 8L * lda + 4);
    vb0 = *(const float4*)(Bp);                 vb1 = *(const float4*)(Bp + 4);
    vb2 = *(const float4*)(Bp + 8L * ldb);      vb3 = *(const float4*)(Bp + 8L * ldb + 4);
    {
        const float* a0 = (const float*)&va0; const float* a1 = (const float*)&va1;
        const float* a2 = (const float*)&va2; const float* a3 = (const float*)&va3;
        const float* b0 = (const float*)&vb0; const float* b1 = (const float*)&vb1;
        const float* b2 = (const float*)&vb2; const float* b3 = (const float*)&vb3;
#pragma unroll
        for (int cc = 0; cc < 4; cc++) {
            sA[0][sbase + cc * 8] = make_float4(tf32r(a0[cc]), tf32r(a2[cc]), tf32r(a1[cc]), tf32r(a3[cc]));
            sB[0][sbase + cc * 8] = make_float4(tf32r(b0[cc]), tf32r(b1[cc]), tf32r(b2[cc]), tf32r(b3[cc]));
        }
    }
    __syncthreads();

    for (int it = 0; it < nIter; it++) {
        int cur  = it & 1;
        bool more = (it + 1) < nIter;
        if (more) {
            long ko = (long)(it + 1) * NBK;
            va0 = *(const float4*)(Ap + ko);            va1 = *(const float4*)(Ap + ko + 4);
            va2 = *(const float4*)(Ap + 8L * lda + ko); va3 = *(const float4*)(Ap + 8L * lda + ko + 4);
            vb0 = *(const float4*)(Bp + ko);            vb1 = *(const float4*)(Bp + ko + 4);
            vb2 = *(const float4*)(Bp + 8L * ldb + ko); vb3 = *(const float4*)(Bp + 8L * ldb + ko + 4);
        }

#pragma unroll
        for (int k2 = 0; k2 < 2; k2++) {
            float4 af[4], bp[4];
            int fb = k2 * 256 + c * 8 + g;
#pragma unroll
            for (int mi = 0; mi < 4; mi++) af[mi] = sA[cur][fb + (jA + mi) * 32];
#pragma unroll
            for (int jj = 0; jj < 4; jj++) bp[jj] = sB[cur][fb + (jB + jj) * 32];
#pragma unroll
            for (int mi = 0; mi < 4; mi++)
#pragma unroll
                for (int jj = 0; jj < 4; jj++) {
                    mma_tf32(acc[mi][2 * jj],     (const uint32_t*)&af[mi], (const uint32_t*)&bp[jj].x);
                    mma_tf32(acc[mi][2 * jj + 1], (const uint32_t*)&af[mi], (const uint32_t*)&bp[jj].z);
                }
        }

        if (more) {
            int nxt = cur ^ 1;
            const float* a0 = (const float*)&va0; const float* a1 = (const float*)&va1;
            const float* a2 = (const float*)&va2; const float* a3 = (const float*)&va3;
            const float* b0 = (const float*)&vb0; const float* b1 = (const float*)&vb1;
            const float* b2 = (const float*)&vb2; const float* b3 = (const float*)&vb3;
#pragma unroll
            for (int cc = 0; cc < 4; cc++) {
                sA[nxt][sbase + cc * 8] = make_float4(tf32r(a0[cc]), tf32r(a2[cc]), tf32r(a1[cc]), tf32r(a3[cc]));
                sB[nxt][sbase + cc * 8] = make_float4(tf32r(b0[cc]), tf32r(b1[cc]), tf32r(b2[cc]), tf32r(b3[cc]));
            }
        }
        __syncthreads();
    }

    // ---- epilogue ----
#pragma unroll
    for (int mi = 0; mi < 4; mi++) {
        int rbase = m0 + wm + mi * 16 + g;
#pragma unroll
        for (int half = 0; half < 2; half++) {
            int gm = rbase + half * 8;
            float*       crow = C + (long)gm * ldc;
            const float* rrow = R ? (R + (long)gm * ldc) : (const float*)0;
#pragma unroll
            for (int ni = 0; ni < 8; ni++) {
                int gn = n0 + wn + ni * 8 + c * 2;
                float v0 = acc[mi][ni][half * 2 + 0] * scale;
                float v1 = acc[mi][ni][half * 2 + 1] * scale;
                if (bias)   { v0 += bias[gn]; v1 += bias[gn + 1]; }
                if (doGelu) { v0 = gelu_f(v0); v1 = gelu_f(v1); }
                if (rrow)   { v0 += rrow[gn]; v1 += rrow[gn + 1]; }
                *(float2*)(crow + gn) = make_float2(v0, v1);
            }
        }
    }
}

// ---------------- tf32 mma.sync batched GEMM (NN path for ctx) ----
#define BM 128
#define BN 128
#define BK 16

__device__ __forceinline__ int slotA_of(int lane) { return lane ^ ((lane >> 2) & 6); }
__device__ __forceinline__ int slotB_of(int lane) { return lane ^ ((lane & 16) >> 3); }

template<bool TRANSB>
__global__ __launch_bounds__(256, 2)
void gemm_tc(const float* __restrict__ A, int lda, long aO1, long aO2,
             const float* __restrict__ B, int ldb, long bO1, long bO2,
             float* __restrict__ C, int ldc, long cO1, long cO2,
             int M, int N, int K,
             const float* __restrict__ bias,
             const float* __restrict__ resid,
             float scale, int doGelu, int causalSkip, int causalKlim, int Hdiv)
{
    int m0 = blockIdx.y * BM;
    int n0 = blockIdx.x * BN;
    if (causalSkip && n0 > m0 + BM - 1) return;

    int z  = blockIdx.z;
    int zb = z / Hdiv, zh = z % Hdiv;
    A += (long)zb * aO1 + (long)zh * aO2;
    B += (long)zb * bO1 + (long)zh * bO2;
    C += (long)zb * cO1 + (long)zh * cO2;
    const float* R = resid ? (resid + (long)zb * cO1 + (long)zh * cO2) : (const float*)0;

    __shared__ float4 sA[2][512];
    __shared__ float2 sB[2][1024];

    int tid  = threadIdx.x;
    int lane = tid & 31, warp = tid >> 5;
    int wm = (warp & 1) * 64;
    int wn = (warp >> 1) * 32;
    int bA0 = wm >> 4;
    int nb0 = wn >> 3;
    int slA = slotA_of(lane);
    int slB = slotB_of(lane);

    float acc[4][4][4];
#pragma unroll
    for (int i = 0; i < 4; i++)
#pragma unroll
        for (int j = 0; j < 4; j++)
#pragma unroll
            for (int r = 0; r < 4; r++) acc[i][j][r] = 0.f;

    int Kend = K;
    if (causalKlim) { int lim = m0 + BM; if (lim < Kend) Kend = lim; }
    int nIter = Kend / BK;

    int am  = tid >> 1;
    int as  = tid & 1;
    int aB  = am >> 4;
    int arr = am & 15;
    int ag  = arr & 7;
    int aRegBase = arr >> 3;
    int aSlot[4];
#pragma unroll
    for (int c = 0; c < 4; c++) aSlot[c] = (ag * 4 + c) ^ (ag & 6);
    const float* Aptr = A + (long)(m0 + am) * lda + as * 8;
    bool aOK = (m0 + am) < M;

    const float* Bptr;
    int bn_nn = 0, bk_nn = 0;
    int bSlot[4];
    if (TRANSB) {
        int bg = arr & 7;
#pragma unroll
        for (int c = 0; c < 4; c++) bSlot[c] = (bg * 4 + c) ^ ((bg & 4) >> 1);
        Bptr = B + (long)(n0 + am) * ldb + as * 8;
    } else {
        bk_nn = tid >> 4;
        bn_nn = (tid & 15) * 8;
#pragma unroll
        for (int j = 0; j < 4; j++) bSlot[j] = 0;
        Bptr = B + (long)bk_nn * ldb + n0 + bn_nn;
    }
    bool bOK = TRANSB ? ((n0 + am) < N) : true;

    float4 pa0, pa1, pb0, pb1;
    {
        pa0 = make_float4(0,0,0,0); pa1 = pa0;
        if (aOK) { pa0 = *(const float4*)(Aptr); pa1 = *(const float4*)(Aptr + 4); }
        pb0 = make_float4(0,0,0,0); pb1 = pb0;
        if (TRANSB) {
            if (bOK) { pb0 = *(const float4*)(Bptr); pb1 = *(const float4*)(Bptr + 4); }
        } else {
            if (n0 + bn_nn     < N) pb0 = *(const float4*)(Bptr);
            if (n0 + bn_nn + 4 < N) pb1 = *(const float4*)(Bptr + 4);
        }
    }
    {
        float va[8] = {pa0.x,pa0.y,pa0.z,pa0.w,pa1.x,pa1.y,pa1.z,pa1.w};
        float* baseA = (float*)&sA[0][(as * 8 + aB) * 32];
#pragma unroll
        for (int kk = 0; kk < 8; kk++)
            baseA[aSlot[kk & 3] * 4 + aRegBase + 2 * (kk >> 2)] = tf32r(va[kk]);
        if (TRANSB) {
            float vb[8] = {pb0.x,pb0.y,pb0.z,pb0.w,pb1.x,pb1.y,pb1.z,pb1.w};
            float2* baseB = &sB[0][(as * 16 + aB * 2 + (arr >> 3)) * 32];
#pragma unroll
            for (int kk = 0; kk < 4; kk++)
                baseB[bSlot[kk]] = make_float2(tf32r(vb[kk]), tf32r(vb[kk + 4]));
        } else {
            float vb[8] = {pb0.x,pb0.y,pb0.z,pb0.w,pb1.x,pb1.y,pb1.z,pb1.w};
            int s  = bk_nn >> 3, kk = bk_nn & 7, c = kk & 3, reg = kk >> 2;
            int nb = bn_nn >> 3;
            float* baseB = (float*)&sB[0][(s * 16 + nb) * 32];
#pragma unroll
            for (int j = 0; j < 8; j++) {
                int slot = (j * 4 + c) ^ ((j & 4) >> 1);
                baseB[slot * 2 + reg] = tf32r(vb[j]);
            }
        }
    }
    __syncthreads();

    for (int it = 0; it < nIter; it++) {
        int cur = it & 1;
        bool more = (it + 1) < nIter;
        if (more) {
            long ko = (long)(it + 1) * BK;
            pa0 = make_float4(0,0,0,0); pa1 = pa0;
            if (aOK) { pa0 = *(const float4*)(Aptr + ko); pa1 = *(const float4*)(Aptr + ko + 4); }
            pb0 = make_float4(0,0,0,0); pb1 = pb0;
            if (TRANSB) {
                if (bOK) { pb0 = *(const float4*)(Bptr + ko); pb1 = *(const float4*)(Bptr + ko + 4); }
            } else {
                const float* bp = Bptr + ko * ldb;
                if (n0 + bn_nn     < N) pb0 = *(const float4*)(bp);
                if (n0 + bn_nn + 4 < N) pb1 = *(const float4*)(bp + 4);
            }
        }

#pragma unroll
        for (int s = 0; s < 2; s++) {
            float4 af[4]; float2 bf[4];
#pragma unroll
            for (int mi = 0; mi < 4; mi++) af[mi] = sA[cur][(s * 8 + bA0 + mi) * 32 + slA];
#pragma unroll
            for (int ni = 0; ni < 4; ni++) bf[ni] = sB[cur][(s * 16 + nb0 + ni) * 32 + slB];
#pragma unroll
            for (int mi = 0; mi < 4; mi++)
#pragma unroll
                for (int ni = 0; ni < 4; ni++)
                    mma_tf32(acc[mi][ni], (const uint32_t*)&af[mi], (const uint32_t*)&bf[ni]);
        }

        if (more) {
            int nxt = cur ^ 1;
            float va[8] = {pa0.x,pa0.y,pa0.z,pa0.w,pa1.x,pa1.y,pa1.z,pa1.w};
            float* baseA = (float*)&sA[nxt][(as * 8 + aB) * 32];
#pragma unroll
            for (int kk = 0; kk < 8; kk++)
                baseA[aSlot[kk & 3] * 4 + aRegBase + 2 * (kk >> 2)] = tf32r(va[kk]);
            float vb[8] = {pb0.x,pb0.y,pb0.z,pb0.w,pb1.x,pb1.y,pb1.z,pb1.w};
            if (TRANSB) {
                float2* baseB = &sB[nxt][(as * 16 + aB * 2 + (arr >> 3)) * 32];
#pragma unroll
                for (int kk = 0; kk < 4; kk++)
                    baseB[bSlot[kk]] = make_float2(tf32r(vb[kk]), tf32r(vb[kk + 4]));
            } else {
                int s  = bk_nn >> 3, kk = bk_nn & 7, c = kk & 3, reg = kk >> 2;
                int nb = bn_nn >> 3;
                float* baseB = (float*)&sB[nxt][(s * 16 + nb) * 32];
#pragma unroll
                for (int j = 0; j < 8; j++) {
                    int slot = (j * 4 + c) ^ ((j & 4) >> 1);
                    baseB[slot * 2 + reg] = tf32r(vb[j]);
                }
            }
        }
        __syncthreads();
    }

    int g = lane >> 2, c2 = (lane & 3) * 2;
#pragma unroll
    for (int mi = 0; mi < 4; mi++) {
#pragma unroll
        for (int ni = 0; ni < 4; ni++) {
            int r0 = m0 + wm + mi * 16 + g;
            int cn = n0 + wn + ni * 8 + c2;
#pragma unroll
            for (int e = 0; e < 4; e++) {
                int gm = r0 + (e >= 2 ? 8 : 0);
                int gn = cn + (e & 1);
                if (gm >= M || gn >= N) continue;
                float vv = acc[mi][ni][e] * scale;
                if (bias)   vv += bias[gn];
                if (doGelu) vv = gelu_f(vv);
                if (R)      vv += R[(long)gm * ldc + gn];
                C[(long)gm * ldc + gn] = vv;
            }
        }
    }
}

// ---------------- dedicated logits kernel (M=2, fp32, memory-bound) ----------
__global__ __launch_bounds__(256)
void logits_k(const float* __restrict__ fin,
              const float* __restrict__ Wemb,
              float* __restrict__ out)
{
    __shared__ float f0[Dc], f1[Dc];
    int tid = threadIdx.x;
    for (int i = tid; i < Dc; i += 256) { f0[i] = fin[i]; f1[i] = fin[Dc + i]; }
    __syncthreads();
    int warp = tid >> 5, lane = tid & 31;
    long v = (long)blockIdx.x * 8 + warp;
    if (v >= Vc) return;
    const float* w = Wemb + v * Dc;
    float d0 = 0.f, d1 = 0.f;
    for (int i = lane * 4; i < Dc; i += 128) {
        float4 wv = *(const float4*)(w + i);
        d0 += wv.x * f0[i] + wv.y * f0[i+1] + wv.z * f0[i+2] + wv.w * f0[i+3];
        d1 += wv.x * f1[i] + wv.y * f1[i+1] + wv.z * f1[i+2] + wv.w * f1[i+3];
    }
#pragma unroll
    for (int o = 16; o > 0; o >>= 1) {
        d0 += __shfl_xor_sync(0xffffffff, d0, o);
        d1 += __shfl_xor_sync(0xffffffff, d1, o);
    }
    if (lane == 0) { out[v] = d0; out[(long)Vc + v] = d1; }
}

// ---------------- host-side launch helpers ----------------
static inline void launch_nt2(const float* A, int lda, long aO1, long aO2,
                              const float* B, int ldb, long bO1, long bO2,
                              float* C, int ldc, long cO1, long cO2,
                              int M, int N, int K,
                              const float* bias, const float* resid,
                              float scale, int gelu, int cskip, int Hdiv, int batch)
{
    dim3 g(N / 128, M / 128, batch);
    gemm_nt2<<<g, 128>>>(A, lda, aO1, aO2, B, ldb, bO1, bO2, C, ldc, cO1, cO2,
                         K, bias, resid, scale, gelu, cskip, Hdiv);
}
static inline void launch_nn(const float* A, int lda, long aO1, long aO2,
                             const float* B, int ldb, long bO1, long bO2,
                             float* C, int ldc, long cO1, long cO2,
                             int M, int N, int K,
                             const float* bias, const float* resid,
                             float scale, int gelu, int cskip, int cklim, int Hdiv, int batch)
{
    dim3 g((N + BN - 1) / BN, (M + BM - 1) / BM, batch);
    gemm_tc<false><<<g, 256>>>(A, lda, aO1, aO2, B, ldb, bO1, bO2, C, ldc, cO1, cO2,
                               M, N, K, bias, resid, scale, gelu, cskip, cklim, Hdiv);
}

extern "C" void kernel_launch(void* const* d_in, const int* in_sizes, int n_in,
                              void* d_out, int out_size)
{
    const int*   x    = (const int*)  d_in[0];
    const float* Wemb = (const float*)d_in[1];
    const float* pos  = (const float*)d_in[2];
    const float* Wq   = (const float*)d_in[3];
    const float* Wk   = (const float*)d_in[4];
    const float* Wv   = (const float*)d_in[5];
    const float* Wo   = (const float*)d_in[6];
    const float* bo   = (const float*)d_in[7];
    const float* n1s  = (const float*)d_in[8];
    const float* n1b  = (const float*)d_in[9];
    const float* n2s  = (const float*)d_in[10];
    const float* n2b  = (const float*)d_in[11];
    const float* W1   = (const float*)d_in[12];
    const float* b1   = (const float*)d_in[13];
    const float* W2   = (const float*)d_in[14];
    const float* b2   = (const float*)d_in[15];
    const float* fs   = (const float*)d_in[16];
    const float* fb   = (const float*)d_in[17];
    float* out = (float*)d_out;

    float *h, *xn, *q, *k, *v, *ctx, *ff, *sc, *fin;
    cudaGetSymbolAddress((void**)&h,   g_h);
    cudaGetSymbolAddress((void**)&xn,  g_xn);
    cudaGetSymbolAddress((void**)&q,   g_q);
    cudaGetSymbolAddress((void**)&k,   g_k);
    cudaGetSymbolAddress((void**)&v,   g_v);
    cudaGetSymbolAddress((void**)&ctx, g_ctx);
    cudaGetSymbolAddress((void**)&ff,  g_ff);
    cudaGetSymbolAddress((void**)&sc,  g_sc);
    cudaGetSymbolAddress((void**)&fin, g_fin);

    const long TD  = (long)Tc * Dc;
    const long TT  = (long)Tc * Tc;
    const int  BH  = Bc * Hc;

    {
        long n = (long)BTc * Dc;
        embed_k<<<(unsigned)((n + 255) / 256), 256>>>(x, Wemb, pos, h);
    }

    for (int l = 0; l < Lc; l++) {
        const float* Wql = Wq + (long)l * Dc * Dc;
        const float* Wkl = Wk + (long)l * Dc * Dc;
        const float* Wvl = Wv + (long)l * Dc * Dc;
        const float* Wol = Wo + (long)l * Dc * Dc;
        const float* bol = bo + (long)l * Dc;
        const float* W1l = W1 + (long)l * DFFc * Dc;
        const float* b1l = b1 + (long)l * DFFc;
        const float* W2l = W2 + (long)l * Dc * DFFc;
        const float* b2l = b2 + (long)l * Dc;

        // LN1
        ln_k<<<BTc, 256>>>(h, Dc, xn, Dc, n1s + (long)l * Dc, n1b + (long)l * Dc);

        // Q,K,V = xn @ W^T
        launch_nt2(xn, Dc, 0, 0, Wql, Dc, 0, 0, q, Dc, 0, 0, BTc, Dc, Dc, 0, 0, 1.f, 0, 0, 1, 1);
        launch_nt2(xn, Dc, 0, 0, Wkl, Dc, 0, 0, k, Dc, 0, 0, BTc, Dc, Dc, 0, 0, 1.f, 0, 0, 1, 1);
        launch_nt2(xn, Dc, 0, 0, Wvl, Dc, 0, 0, v, Dc, 0, 0, BTc, Dc, Dc, 0, 0, 1.f, 0, 0, 1, 1);

        // scores = (Q.K)/8 with causal block skip, batched over z=(b,h)
        launch_nt2(q, Dc, TD, HDc, k, Dc, TD, HDc,
                   sc, Tc, (long)Hc * TT, TT,
                   Tc, Tc, HDc, 0, 0, 1.0f / 8.0f, 0, /*cskip=*/1, Hc, BH);

        // causal softmax in-place
        softmax_k<<<(unsigned)(BH * Tc), 256>>>(sc);

        // ctx = P @ V  (NN, causal K limit)
        launch_nn(sc, Tc, (long)Hc * TT, TT, v, Dc, TD, HDc,
                  ctx, Dc, TD, HDc,
                  Tc, HDc, Tc, 0, 0, 1.f, 0, 0, /*cklim=*/1, Hc, BH);

        // h = h + ctx @ Wo^T + bo
        launch_nt2(ctx, Dc, 0, 0, Wol, Dc, 0, 0, h, Dc, 0, 0, BTc, Dc, Dc, bol, h, 1.f, 0, 0, 1, 1);

        // LN2
        ln_k<<<BTc, 256>>>(h, Dc, xn, Dc, n2s + (long)l * Dc, n2b + (long)l * Dc);

        // ff = gelu(xn @ W1^T + b1)
        launch_nt2(xn, Dc, 0, 0, W1l, Dc, 0, 0, ff, DFFc, 0, 0, BTc, DFFc, Dc, b1l, 0, 1.f, 1, 0, 1, 1);

        // h = h + ff @ W2^T + b2
        launch_nt2(ff, DFFc, 0, 0, W2l, DFFc, 0, 0, h, Dc, 0, 0, BTc, Dc, DFFc, b2l, h, 1.f, 0, 0, 1, 1);
    }

    // final LN on the 2 last-token rows only
    ln_k<<<Bc, 256>>>(h + (long)(Tc - 1) * Dc, TD, fin, Dc, fs, fb);

    // logits (fp32, memory-bound dedicated kernel)
    logits_k<<<(Vc + 7) / 8, 256>>>(fin, Wemb, out);
}

// round 6
// speedup vs baseline: 1.0053x; 1.0053x over previous
#include <cuda_runtime.h>
#include <cuda_bf16.h>
#include <math.h>
#include <stdint.h>

// ---------------- problem constants ----------------
#define Bc   2
#define Tc   2048
#define Dc   1024
#define Hc   16
#define HDc  64
#define DFFc 4096
#define Lc   8
#define Vc   50257
#define BTc  (Bc*Tc)          // 4096
#define EPSc 1e-5f

// ---------------- static device scratch (no allocs allowed) ----------------
__device__ float g_h  [BTc*Dc];
__device__ float g_xn [BTc*Dc];
__device__ float g_q  [BTc*Dc];
__device__ float g_k  [BTc*Dc];
__device__ float g_v  [BTc*Dc];
__device__ float g_ctx[BTc*Dc];
__device__ float g_ff [(long)BTc*DFFc];
__device__ float g_sc [(long)Bc*Hc*Tc*Tc];   // scores / probs (in-place softmax)
__device__ float g_fin[Bc*Dc];               // final-LN of last tokens

// ---------------- helpers ----------------
__device__ __forceinline__ float gelu_f(float x) {
    const float c = 0.7978845608028654f;
    return 0.5f * x * (1.0f + tanhf(c * (x + 0.044715f * x * x * x)));
}
__device__ __forceinline__ float tf32r(float x) {
    uint32_t u;
    asm("cvt.rna.tf32.f32 %0, %1;" : "=r"(u) : "f"(x));
    return __uint_as_float(u);
}
__device__ __forceinline__ void mma_tf32(float* c, const uint32_t* a, const uint32_t* b) {
    asm volatile(
        "mma.sync.aligned.m16n8k8.row.col.f32.tf32.tf32.f32 "
        "{%0,%1,%2,%3}, {%4,%5,%6,%7}, {%8,%9}, {%0,%1,%2,%3};"
        : "+f"(c[0]), "+f"(c[1]), "+f"(c[2]), "+f"(c[3])
        : "r"(a[0]), "r"(a[1]), "r"(a[2]), "r"(a[3]), "r"(b[0]), "r"(b[1]));
}

// ---------------- embedding ----------------
__global__ void embed_k(const int* __restrict__ x,
                        const float* __restrict__ Wemb,
                        const float* __restrict__ pos,
                        float* __restrict__ h)
{
    long i = (long)blockIdx.x * blockDim.x + threadIdx.x;
    if (i >= (long)BTc * Dc) return;
    int row = (int)(i / Dc);
    int d   = (int)(i % Dc);
    int t   = row % Tc;
    int tok = x[row];
    h[i] = Wemb[(long)tok * Dc + d] + pos[(long)t * Dc + d];
}

// ---------------- layernorm (ddof=1, std+eps) ----------------
__global__ void ln_k(const float* __restrict__ in, long inStride,
                     float* __restrict__ out, long outStride,
                     const float* __restrict__ sc, const float* __restrict__ sh)
{
    __shared__ float red[256];
    int r = blockIdx.x, tid = threadIdx.x;
    const float* x = in + (long)r * inStride;
    float xv[4];
    float s = 0.f;
#pragma unroll
    for (int i = 0; i < 4; i++) { xv[i] = x[tid + i * 256]; s += xv[i]; }
    red[tid] = s; __syncthreads();
    for (int st = 128; st > 0; st >>= 1) { if (tid < st) red[tid] += red[tid + st]; __syncthreads(); }
    float mean = red[0] * (1.0f / (float)Dc);
    __syncthreads();
    float v = 0.f;
#pragma unroll
    for (int i = 0; i < 4; i++) { float t = xv[i] - mean; v += t * t; }
    red[tid] = v; __syncthreads();
    for (int st = 128; st > 0; st >>= 1) { if (tid < st) red[tid] += red[tid + st]; __syncthreads(); }
    float inv = 1.0f / (sqrtf(red[0] / (float)(Dc - 1)) + EPSc);
    float* o = out + (long)r * outStride;
#pragma unroll
    for (int i = 0; i < 4; i++) { int d = tid + i * 256; o[d] = sc[d] * ((xv[i] - mean) * inv) + sh[d]; }
}

// ---------------- causal softmax ----------------
__global__ void softmax_k(float* __restrict__ S)
{
    long row = blockIdx.x;                 // = z*T + q
    int  q   = (int)(row % Tc);
    float* p = S + row * (long)Tc;
    int len  = q + 1;
    int tid  = threadIdx.x;
    __shared__ float red[256];

    float mx = -1e30f;
    for (int k = tid; k < len; k += 256) mx = fmaxf(mx, p[k]);
    red[tid] = mx; __syncthreads();
    for (int st = 128; st > 0; st >>= 1) { if (tid < st) red[tid] = fmaxf(red[tid], red[tid + st]); __syncthreads(); }
    mx = red[0]; __syncthreads();

    float sum = 0.f;
    for (int k = tid; k < len; k += 256) sum += expf(p[k] - mx);
    red[tid] = sum; __syncthreads();
    for (int st = 128; st > 0; st >>= 1) { if (tid < st) red[tid] += red[tid + st]; __syncthreads(); }
    float inv = 1.0f / red[0];

    for (int k = tid; k < len; k += 256) p[k] = expf(p[k] - mx) * inv;
    int kzend = ((q >> 7) + 1) << 7; if (kzend > Tc) kzend = Tc;
    for (int k = len + tid; k < kzend; k += 256) p[k] = 0.f;
}

// =====================================================================
// gemm_nt3: NT GEMM, 128(M)x256(N) block, 8 warps of 64x64 tiles, 256 thr.
// Requires: M % 128 == 0, N % 256 == 0, K % 16 == 0.
// C = scale*(A[M,K] @ B[N,K]^T) [+bias][gelu][+resid]
// Fragment-slot smem layout (verified in R5):
//   slot(ks, j, gs, cc) = {X[16j+gs][8ks+cc], X[16j+8+gs][8ks+cc],
//                          X[16j+gs][8ks+cc+4], X[16j+8+gs][8ks+cc+4]}  (A order)
//   B slots store {B[r][c], B[r][c+4], B[r+8][c], B[r+8][c+4]}.
// =====================================================================
#define NBK 16

__global__ __launch_bounds__(256, 1)
void gemm_nt3(const float* __restrict__ A, int lda, long aO1, long aO2,
              const float* __restrict__ B, int ldb, long bO1, long bO2,
              float* __restrict__ C, int ldc, long cO1, long cO2,
              int K,
              const float* __restrict__ bias,
              const float* __restrict__ resid,
              float scale, int doGelu, int causalSkip, int Hdiv)
{
    int m0 = blockIdx.y * 128;
    int n0 = blockIdx.x * 256;
    if (causalSkip && n0 > m0 + 127) return;

    int z  = blockIdx.z;
    int zb = z / Hdiv, zh = z % Hdiv;
    A += (long)zb * aO1 + (long)zh * aO2;
    B += (long)zb * bO1 + (long)zh * bO2;
    C += (long)zb * cO1 + (long)zh * cO2;
    const float* R = resid ? (resid + (long)zb * cO1 + (long)zh * cO2) : (const float*)0;

    __shared__ float4 sA[2][512];    // 8 KB/stage  (128 rows)
    __shared__ float4 sB[2][1024];   // 16 KB/stage (256 rows)

    int tid  = threadIdx.x;
    int lane = tid & 31, warp = tid >> 5;
    int wm = (warp & 1) * 64;          // 2 warps along M
    int wn = (warp >> 1) * 64;         // 4 warps along N
    int jA = wm >> 4, jB = wn >> 4;
    int g  = lane >> 2, c = lane & 3;

    float acc[4][8][4];
#pragma unroll
    for (int i = 0; i < 4; i++)
#pragma unroll
        for (int j = 0; j < 8; j++)
#pragma unroll
            for (int e = 0; e < 4; e++) acc[i][j][e] = 0.f;

    // ---- A staging role (threads 0..127) ----
    bool doA = tid < 128;
    int ksA = (tid >> 6) & 1;
    int prA = tid & 63;
    int jsA = prA >> 3, gsA = prA & 7;
    int rA  = jsA * 16 + gsA;
    const float* Ap = A + (long)(m0 + rA) * lda + ksA * 8;
    int sbA = ksA * 256 + jsA * 32 + gsA;

    // ---- B staging role (all 256 threads) ----
    int ksB = tid >> 7;
    int prB = tid & 127;
    int jsB = prB >> 3, gsB = prB & 7;
    int rB  = jsB * 16 + gsB;
    const float* Bp = B + (long)(n0 + rB) * ldb + ksB * 8;
    int sbB = ksB * 512 + jsB * 32 + gsB;

    int nIter = K / NBK;

    float4 va0, va1, va2, va3, vb0, vb1, vb2, vb3;
    // prologue
    if (doA) {
        va0 = *(const float4*)(Ap);            va1 = *(const float4*)(Ap + 4);
        va2 = *(const float4*)(Ap + 8L * lda); va3 = *(const float4*)(Ap + 8L * lda + 4);
    }
    vb0 = *(const float4*)(Bp);            vb1 = *(const float4*)(Bp + 4);
    vb2 = *(const float4*)(Bp + 8L * ldb); vb3 = *(const float4*)(Bp + 8L * ldb + 4);
    {
        if (doA) {
            const float* a0 = (const float*)&va0; const float* a1 = (const float*)&va1;
            const float* a2 = (const float*)&va2; const float* a3 = (const float*)&va3;
#pragma unroll
            for (int cc = 0; cc < 4; cc++)
                sA[0][sbA + cc * 8] = make_float4(tf32r(a0[cc]), tf32r(a2[cc]), tf32r(a1[cc]), tf32r(a3[cc]));
        }
        const float* b0 = (const float*)&vb0; const float* b1 = (const float*)&vb1;
        const float* b2 = (const float*)&vb2; const float* b3 = (const float*)&vb3;
#pragma unroll
        for (int cc = 0; cc < 4; cc++)
            sB[0][sbB + cc * 8] = make_float4(tf32r(b0[cc]), tf32r(b1[cc]), tf32r(b2[cc]), tf32r(b3[cc]));
    }
    __syncthreads();

    for (int it = 0; it < nIter; it++) {
        int cur  = it & 1;
        bool more = (it + 1) < nIter;
        if (more) {
            long ko = (long)(it + 1) * NBK;
            if (doA) {
                va0 = *(const float4*)(Ap + ko);            va1 = *(const float4*)(Ap + ko + 4);
                va2 = *(const float4*)(Ap + 8L * lda + ko); va3 = *(const float4*)(Ap + 8L * lda + ko + 4);
            }
            vb0 = *(const float4*)(Bp + ko);            vb1 = *(const float4*)(Bp + ko + 4);
            vb2 = *(const float4*)(Bp + 8L * ldb + ko); vb3 = *(const float4*)(Bp + 8L * ldb + ko + 4);
        }

#pragma unroll
        for (int k2 = 0; k2 < 2; k2++) {
            float4 af[4], bp4[4];
            int fbA = k2 * 256 + c * 8 + g;
            int fbB = k2 * 512 + c * 8 + g;
#pragma unroll
            for (int mi = 0; mi < 4; mi++) af[mi]  = sA[cur][fbA + (jA + mi) * 32];
#pragma unroll
            for (int jj = 0; jj < 4; jj++) bp4[jj] = sB[cur][fbB + (jB + jj) * 32];
#pragma unroll
            for (int mi = 0; mi < 4; mi++)
#pragma unroll
                for (int jj = 0; jj < 4; jj++) {
                    mma_tf32(acc[mi][2 * jj],     (const uint32_t*)&af[mi], (const uint32_t*)&bp4[jj].x);
                    mma_tf32(acc[mi][2 * jj + 1], (const uint32_t*)&af[mi], (const uint32_t*)&bp4[jj].z);
                }
        }

        if (more) {
            int nxt = cur ^ 1;
            if (doA) {
                const float* a0 = (const float*)&va0; const float* a1 = (const float*)&va1;
                const float* a2 = (const float*)&va2; const float* a3 = (const float*)&va3;
#pragma unroll
                for (int cc = 0; cc < 4; cc++)
                    sA[nxt][sbA + cc * 8] = make_float4(tf32r(a0[cc]), tf32r(a2[cc]), tf32r(a1[cc]), tf32r(a3[cc]));
            }
            const float* b0 = (const float*)&vb0; const float* b1 = (const float*)&vb1;
            const float* b2 = (const float*)&vb2; const float* b3 = (const float*)&vb3;
#pragma unroll
            for (int cc = 0; cc < 4; cc++)
                sB[nxt][sbB + cc * 8] = make_float4(tf32r(b0[cc]), tf32r(b1[cc]), tf32r(b2[cc]), tf32r(b3[cc]));
        }
        __syncthreads();
    }

    // ---- epilogue ----
#pragma unroll
    for (int mi = 0; mi < 4; mi++) {
        int rbase = m0 + wm + mi * 16 + g;
#pragma unroll
        for (int half = 0; half < 2; half++) {
            int gm = rbase + half * 8;
            float*       crow = C + (long)gm * ldc;
            const float* rrow = R ? (R + (long)gm * ldc) : (const float*)0;
#pragma unroll
            for (int ni = 0; ni < 8; ni++) {
                int gn = n0 + wn + ni * 8 + c * 2;
                float v0 = acc[mi][ni][half * 2 + 0] * scale;
                float v1 = acc[mi][ni][half * 2 + 1] * scale;
                if (bias)   { v0 += bias[gn]; v1 += bias[gn + 1]; }
                if (doGelu) { v0 = gelu_f(v0); v1 = gelu_f(v1); }
                if (rrow)   { v0 += rrow[gn]; v1 += rrow[gn + 1]; }
                *(float2*)(crow + gn) = make_float2(v0, v1);
            }
        }
    }
}

// ---------------- tf32 mma.sync batched GEMM (NN path for ctx) ----
#define BM 128
#define BN 128
#define BK 16

__device__ __forceinline__ int slotA_of(int lane) { return lane ^ ((lane >> 2) & 6); }
__device__ __forceinline__ int slotB_of(int lane) { return lane ^ ((lane & 16) >> 3); }

template<bool TRANSB>
__global__ __launch_bounds__(256, 2)
void gemm_tc(const float* __restrict__ A, int lda, long aO1, long aO2,
             const float* __restrict__ B, int ldb, long bO1, long bO2,
             float* __restrict__ C, int ldc, long cO1, long cO2,
             int M, int N, int K,
             const float* __restrict__ bias,
             const float* __restrict__ resid,
             float scale, int doGelu, int causalSkip, int causalKlim, int Hdiv)
{
    int m0 = blockIdx.y * BM;
    int n0 = blockIdx.x * BN;
    if (causalSkip && n0 > m0 + BM - 1) return;

    int z  = blockIdx.z;
    int zb = z / Hdiv, zh = z % Hdiv;
    A += (long)zb * aO1 + (long)zh * aO2;
    B += (long)zb * bO1 + (long)zh * bO2;
    C += (long)zb * cO1 + (long)zh * cO2;
    const float* R = resid ? (resid + (long)zb * cO1 + (long)zh * cO2) : (const float*)0;

    __shared__ float4 sA[2][512];
    __shared__ float2 sB[2][1024];

    int tid  = threadIdx.x;
    int lane = tid & 31, warp = tid >> 5;
    int wm = (warp & 1) * 64;
    int wn = (warp >> 1) * 32;
    int bA0 = wm >> 4;
    int nb0 = wn >> 3;
    int slA = slotA_of(lane);
    int slB = slotB_of(lane);

    float acc[4][4][4];
#pragma unroll
    for (int i = 0; i < 4; i++)
#pragma unroll
        for (int j = 0; j < 4; j++)
#pragma unroll
            for (int r = 0; r < 4; r++) acc[i][j][r] = 0.f;

    int Kend = K;
    if (causalKlim) { int lim = m0 + BM; if (lim < Kend) Kend = lim; }
    int nIter = Kend / BK;

    int am  = tid >> 1;
    int as  = tid & 1;
    int aB  = am >> 4;
    int arr = am & 15;
    int ag  = arr & 7;
    int aRegBase = arr >> 3;
    int aSlot[4];
#pragma unroll
    for (int c = 0; c < 4; c++) aSlot[c] = (ag * 4 + c) ^ (ag & 6);
    const float* Aptr = A + (long)(m0 + am) * lda + as * 8;
    bool aOK = (m0 + am) < M;

    const float* Bptr;
    int bn_nn = 0, bk_nn = 0;
    int bSlot[4];
    if (TRANSB) {
        int bg = arr & 7;
#pragma unroll
        for (int c = 0; c < 4; c++) bSlot[c] = (bg * 4 + c) ^ ((bg & 4) >> 1);
        Bptr = B + (long)(n0 + am) * ldb + as * 8;
    } else {
        bk_nn = tid >> 4;
        bn_nn = (tid & 15) * 8;
#pragma unroll
        for (int j = 0; j < 4; j++) bSlot[j] = 0;
        Bptr = B + (long)bk_nn * ldb + n0 + bn_nn;
    }
    bool bOK = TRANSB ? ((n0 + am) < N) : true;

    float4 pa0, pa1, pb0, pb1;
    {
        pa0 = make_float4(0,0,0,0); pa1 = pa0;
        if (aOK) { pa0 = *(const float4*)(Aptr); pa1 = *(const float4*)(Aptr + 4); }
        pb0 = make_float4(0,0,0,0); pb1 = pb0;
        if (TRANSB) {
            if (bOK) { pb0 = *(const float4*)(Bptr); pb1 = *(const float4*)(Bptr + 4); }
        } else {
            if (n0 + bn_nn     < N) pb0 = *(const float4*)(Bptr);
            if (n0 + bn_nn + 4 < N) pb1 = *(const float4*)(Bptr + 4);
        }
    }
    {
        float va[8] = {pa0.x,pa0.y,pa0.z,pa0.w,pa1.x,pa1.y,pa1.z,pa1.w};
        float* baseA = (float*)&sA[0][(as * 8 + aB) * 32];
#pragma unroll
        for (int kk = 0; kk < 8; kk++)
            baseA[aSlot[kk & 3] * 4 + aRegBase + 2 * (kk >> 2)] = tf32r(va[kk]);
        if (TRANSB) {
            float vb[8] = {pb0.x,pb0.y,pb0.z,pb0.w,pb1.x,pb1.y,pb1.z,pb1.w};
            float2* baseB = &sB[0][(as * 16 + aB * 2 + (arr >> 3)) * 32];
#pragma unroll
            for (int kk = 0; kk < 4; kk++)
                baseB[bSlot[kk]] = make_float2(tf32r(vb[kk]), tf32r(vb[kk + 4]));
        } else {
            float vb[8] = {pb0.x,pb0.y,pb0.z,pb0.w,pb1.x,pb1.y,pb1.z,pb1.w};
            int s  = bk_nn >> 3, kk = bk_nn & 7, c = kk & 3, reg = kk >> 2;
            int nb = bn_nn >> 3;
            float* baseB = (float*)&sB[0][(s * 16 + nb) * 32];
#pragma unroll
            for (int j = 0; j < 8; j++) {
                int slot = (j * 4 + c) ^ ((j & 4) >> 1);
                baseB[slot * 2 + reg] = tf32r(vb[j]);
            }
        }
    }
    __syncthreads();

    for (int it = 0; it < nIter; it++) {
        int cur = it & 1;
        bool more = (it + 1) < nIter;
        if (more) {
            long ko = (long)(it + 1) * BK;
            pa0 = make_float4(0,0,0,0); pa1 = pa0;
            if (aOK) { pa0 = *(const float4*)(Aptr + ko); pa1 = *(const float4*)(Aptr + ko + 4); }
            pb0 = make_float4(0,0,0,0); pb1 = pb0;
            if (TRANSB) {
                if (bOK) { pb0 = *(const float4*)(Bptr + ko); pb1 = *(const float4*)(Bptr + ko + 4); }
            } else {
                const float* bp = Bptr + ko * ldb;
                if (n0 + bn_nn     < N) pb0 = *(const float4*)(bp);
                if (n0 + bn_nn + 4 < N) pb1 = *(const float4*)(bp + 4);
            }
        }

#pragma unroll
        for (int s = 0; s < 2; s++) {
            float4 af[4]; float2 bf[4];
#pragma unroll
            for (int mi = 0; mi < 4; mi++) af[mi] = sA[cur][(s * 8 + bA0 + mi) * 32 + slA];
#pragma unroll
            for (int ni = 0; ni < 4; ni++) bf[ni] = sB[cur][(s * 16 + nb0 + ni) * 32 + slB];
#pragma unroll
            for (int mi = 0; mi < 4; mi++)
#pragma unroll
                for (int ni = 0; ni < 4; ni++)
                    mma_tf32(acc[mi][ni], (const uint32_t*)&af[mi], (const uint32_t*)&bf[ni]);
        }

        if (more) {
            int nxt = cur ^ 1;
            float va[8] = {pa0.x,pa0.y,pa0.z,pa0.w,pa1.x,pa1.y,pa1.z,pa1.w};
            float* baseA = (float*)&sA[nxt][(as * 8 + aB) * 32];
#pragma unroll
            for (int kk = 0; kk < 8; kk++)
                baseA[aSlot[kk & 3] * 4 + aRegBase + 2 * (kk >> 2)] = tf32r(va[kk]);
            float vb[8] = {pb0.x,pb0.y,pb0.z,pb0.w,pb1.x,pb1.y,pb1.z,pb1.w};
            if (TRANSB) {
                float2* baseB = &sB[nxt][(as * 16 + aB * 2 + (arr >> 3)) * 32];
#pragma unroll
                for (int kk = 0; kk < 4; kk++)
                    baseB[bSlot[kk]] = make_float2(tf32r(vb[kk]), tf32r(vb[kk + 4]));
            } else {
                int s  = bk_nn >> 3, kk = bk_nn & 7, c = kk & 3, reg = kk >> 2;
                int nb = bn_nn >> 3;
                float* baseB = (float*)&sB[nxt][(s * 16 + nb) * 32];
#pragma unroll
                for (int j = 0; j < 8; j++) {
                    int slot = (j * 4 + c) ^ ((j & 4) >> 1);
                    baseB[slot * 2 + reg] = tf32r(vb[j]);
                }
            }
        }
        __syncthreads();
    }

    int g = lane >> 2, c2 = (lane & 3) * 2;
#pragma unroll
    for (int mi = 0; mi < 4; mi++) {
#pragma unroll
        for (int ni = 0; ni < 4; ni++) {
            int r0 = m0 + wm + mi * 16 + g;
            int cn = n0 + wn + ni * 8 + c2;
#pragma unroll
            for (int e = 0; e < 4; e++) {
                int gm = r0 + (e >= 2 ? 8 : 0);
                int gn = cn + (e & 1);
                if (gm >= M || gn >= N) continue;
                float vv = acc[mi][ni][e] * scale;
                if (bias)   vv += bias[gn];
                if (doGelu) vv = gelu_f(vv);
                if (R)      vv += R[(long)gm * ldc + gn];
                C[(long)gm * ldc + gn] = vv;
            }
        }
    }
}

// ---------------- dedicated logits kernel (M=2, fp32, memory-bound) ----------
__global__ __launch_bounds__(256)
void logits_k(const float* __restrict__ fin,
              const float* __restrict__ Wemb,
              float* __restrict__ out)
{
    __shared__ float f0[Dc], f1[Dc];
    int tid = threadIdx.x;
    for (int i = tid; i < Dc; i += 256) { f0[i] = fin[i]; f1[i] = fin[Dc + i]; }
    __syncthreads();
    int warp = tid >> 5, lane = tid & 31;
    long v = (long)blockIdx.x * 8 + warp;
    if (v >= Vc) return;
    const float* w = Wemb + v * Dc;
    float d0 = 0.f, d1 = 0.f;
    for (int i = lane * 4; i < Dc; i += 128) {
        float4 wv = *(const float4*)(w + i);
        d0 += wv.x * f0[i] + wv.y * f0[i+1] + wv.z * f0[i+2] + wv.w * f0[i+3];
        d1 += wv.x * f1[i] + wv.y * f1[i+1] + wv.z * f1[i+2] + wv.w * f1[i+3];
    }
#pragma unroll
    for (int o = 16; o > 0; o >>= 1) {
        d0 += __shfl_xor_sync(0xffffffff, d0, o);
        d1 += __shfl_xor_sync(0xffffffff, d1, o);
    }
    if (lane == 0) { out[v] = d0; out[(long)Vc + v] = d1; }
}

// ---------------- host-side launch helpers ----------------
static inline void launch_nt3(const float* A, int lda, long aO1, long aO2,
                              const float* B, int ldb, long bO1, long bO2,
                              float* C, int ldc, long cO1, long cO2,
                              int M, int N, int K,
                              const float* bias, const float* resid,
                              float scale, int gelu, int cskip, int Hdiv, int batch)
{
    dim3 g(N / 256, M / 128, batch);
    gemm_nt3<<<g, 256>>>(A, lda, aO1, aO2, B, ldb, bO1, bO2, C, ldc, cO1, cO2,
                         K, bias, resid, scale, gelu, cskip, Hdiv);
}
static inline void launch_nn(const float* A, int lda, long aO1, long aO2,
                             const float* B, int ldb, long bO1, long bO2,
                             float* C, int ldc, long cO1, long cO2,
                             int M, int N, int K,
                             const float* bias, const float* resid,
                             float scale, int gelu, int cskip, int cklim, int Hdiv, int batch)
{
    dim3 g((N + BN - 1) / BN, (M + BM - 1) / BM, batch);
    gemm_tc<false><<<g, 256>>>(A, lda, aO1, aO2, B, ldb, bO1, bO2, C, ldc, cO1, cO2,
                               M, N, K, bias, resid, scale, gelu, cskip, cklim, Hdiv);
}

extern "C" void kernel_launch(void* const* d_in, const int* in_sizes, int n_in,
                              void* d_out, int out_size)
{
    const int*   x    = (const int*)  d_in[0];
    const float* Wemb = (const float*)d_in[1];
    const float* pos  = (const float*)d_in[2];
    const float* Wq   = (const float*)d_in[3];
    const float* Wk   = (const float*)d_in[4];
    const float* Wv   = (const float*)d_in[5];
    const float* Wo   = (const float*)d_in[6];
    const float* bo   = (const float*)d_in[7];
    const float* n1s  = (const float*)d_in[8];
    const float* n1b  = (const float*)d_in[9];
    const float* n2s  = (const float*)d_in[10];
    const float* n2b  = (const float*)d_in[11];
    const float* W1   = (const float*)d_in[12];
    const float* b1   = (const float*)d_in[13];
    const float* W2   = (const float*)d_in[14];
    const float* b2   = (const float*)d_in[15];
    const float* fs   = (const float*)d_in[16];
    const float* fb   = (const float*)d_in[17];
    float* out = (float*)d_out;

    float *h, *xn, *q, *k, *v, *ctx, *ff, *sc, *fin;
    cudaGetSymbolAddress((void**)&h,   g_h);
    cudaGetSymbolAddress((void**)&xn,  g_xn);
    cudaGetSymbolAddress((void**)&q,   g_q);
    cudaGetSymbolAddress((void**)&k,   g_k);
    cudaGetSymbolAddress((void**)&v,   g_v);
    cudaGetSymbolAddress((void**)&ctx, g_ctx);
    cudaGetSymbolAddress((void**)&ff,  g_ff);
    cudaGetSymbolAddress((void**)&sc,  g_sc);
    cudaGetSymbolAddress((void**)&fin, g_fin);

    const long TD  = (long)Tc * Dc;
    const long TT  = (long)Tc * Tc;
    const int  BH  = Bc * Hc;

    {
        long n = (long)BTc * Dc;
        embed_k<<<(unsigned)((n + 255) / 256), 256>>>(x, Wemb, pos, h);
    }

    for (int l = 0; l < Lc; l++) {
        const float* Wql = Wq + (long)l * Dc * Dc;
        const float* Wkl = Wk + (long)l * Dc * Dc;
        const float* Wvl = Wv + (long)l * Dc * Dc;
        const float* Wol = Wo + (long)l * Dc * Dc;
        const float* bol = bo + (long)l * Dc;
        const float* W1l = W1 + (long)l * DFFc * Dc;
        const float* b1l = b1 + (long)l * DFFc;
        const float* W2l = W2 + (long)l * Dc * DFFc;
        const float* b2l = b2 + (long)l * Dc;

        // LN1
        ln_k<<<BTc, 256>>>(h, Dc, xn, Dc, n1s + (long)l * Dc, n1b + (long)l * Dc);

        // Q,K,V = xn @ W^T
        launch_nt3(xn, Dc, 0, 0, Wql, Dc, 0, 0, q, Dc, 0, 0, BTc, Dc, Dc, 0, 0, 1.f, 0, 0, 1, 1);
        launch_nt3(xn, Dc, 0, 0, Wkl, Dc, 0, 0, k, Dc, 0, 0, BTc, Dc, Dc, 0, 0, 1.f, 0, 0, 1, 1);
        launch_nt3(xn, Dc, 0, 0, Wvl, Dc, 0, 0, v, Dc, 0, 0, BTc, Dc, Dc, 0, 0, 1.f, 0, 0, 1, 1);

        // scores = (Q.K)/8 with causal block skip, batched over z=(b,h)
        launch_nt3(q, Dc, TD, HDc, k, Dc, TD, HDc,
                   sc, Tc, (long)Hc * TT, TT,
                   Tc, Tc, HDc, 0, 0, 1.0f / 8.0f, 0, /*cskip=*/1, Hc, BH);

        // causal softmax in-place
        softmax_k<<<(unsigned)(BH * Tc), 256>>>(sc);

        // ctx = P @ V  (NN, causal K limit)
        launch_nn(sc, Tc, (long)Hc * TT, TT, v, Dc, TD, HDc,
                  ctx, Dc, TD, HDc,
                  Tc, HDc, Tc, 0, 0, 1.f, 0, 0, /*cklim=*/1, Hc, BH);

        // h = h + ctx @ Wo^T + bo
        launch_nt3(ctx, Dc, 0, 0, Wol, Dc, 0, 0, h, Dc, 0, 0, BTc, Dc, Dc, bol, h, 1.f, 0, 0, 1, 1);

        // LN2
        ln_k<<<BTc, 256>>>(h, Dc, xn, Dc, n2s + (long)l * Dc, n2b + (long)l * Dc);

        // ff = gelu(xn @ W1^T + b1)
        launch_nt3(xn, Dc, 0, 0, W1l, Dc, 0, 0, ff, DFFc, 0, 0, BTc, DFFc, Dc, b1l, 0, 1.f, 1, 0, 1, 1);

        // h = h + ff @ W2^T + b2
        launch_nt3(ff, DFFc, 0, 0, W2l, DFFc, 0, 0, h, Dc, 0, 0, BTc, Dc, DFFc, b2l, h, 1.f, 0, 0, 1, 1);
    }

    // final LN on the 2 last-token rows only
    ln_k<<<Bc, 256>>>(h + (long)(Tc - 1) * Dc, TD, fin, Dc, fs, fb);

    // logits (fp32, memory-bound dedicated kernel)
    logits_k<<<(Vc + 7) / 8, 256>>>(fin, Wemb, out);
}

// round 7
// speedup vs baseline: 1.3762x; 1.3690x over previous
#include <cuda_runtime.h>
#include <cuda_bf16.h>
#include <math.h>
#include <stdint.h>

// ---------------- problem constants ----------------
#define Bc   2
#define Tc   2048
#define Dc   1024
#define Hc   16
#define HDc  64
#define DFFc 4096
#define Lc   8
#define Vc   50257
#define BTc  (Bc*Tc)          // 4096
#define EPSc 1e-5f

// ---------------- static device scratch (no allocs allowed) ----------------
__device__ float g_h  [BTc*Dc];
__device__ float g_xn [BTc*Dc];
__device__ float g_q  [BTc*Dc];
__device__ float g_k  [BTc*Dc];
__device__ float g_v  [BTc*Dc];
__device__ float g_ctx[BTc*Dc];
__device__ float g_ff [(long)BTc*DFFc];
__device__ float g_sc [(long)Bc*Hc*Tc*Tc];   // scores / probs (in-place softmax)
__device__ float g_fin[Bc*Dc];               // final-LN of last tokens

// ---------------- helpers ----------------
__device__ __forceinline__ float gelu_f(float x) {
    const float c = 0.7978845608028654f;
    return 0.5f * x * (1.0f + tanhf(c * (x + 0.044715f * x * x * x)));
}
__device__ __forceinline__ float tf32r(float x) {
    uint32_t u;
    asm("cvt.rna.tf32.f32 %0, %1;" : "=r"(u) : "f"(x));
    return __uint_as_float(u);
}
__device__ __forceinline__ void mma_tf32(float* c, const uint32_t* a, const uint32_t* b) {
    asm volatile(
        "mma.sync.aligned.m16n8k8.row.col.f32.tf32.tf32.f32 "
        "{%0,%1,%2,%3}, {%4,%5,%6,%7}, {%8,%9}, {%0,%1,%2,%3};"
        : "+f"(c[0]), "+f"(c[1]), "+f"(c[2]), "+f"(c[3])
        : "r"(a[0]), "r"(a[1]), "r"(a[2]), "r"(a[3]), "r"(b[0]), "r"(b[1]));
}

// ---------------- embedding ----------------
__global__ void embed_k(const int* __restrict__ x,
                        const float* __restrict__ Wemb,
                        const float* __restrict__ pos,
                        float* __restrict__ h)
{
    long i = (long)blockIdx.x * blockDim.x + threadIdx.x;
    if (i >= (long)BTc * Dc) return;
    int row = (int)(i / Dc);
    int d   = (int)(i % Dc);
    int t   = row % Tc;
    int tok = x[row];
    h[i] = Wemb[(long)tok * Dc + d] + pos[(long)t * Dc + d];
}

// ---------------- layernorm (ddof=1, std+eps) ----------------
__global__ void ln_k(const float* __restrict__ in, long inStride,
                     float* __restrict__ out, long outStride,
                     const float* __restrict__ sc, const float* __restrict__ sh)
{
    __shared__ float red[256];
    int r = blockIdx.x, tid = threadIdx.x;
    const float* x = in + (long)r * inStride;
    float xv[4];
    float s = 0.f;
#pragma unroll
    for (int i = 0; i < 4; i++) { xv[i] = x[tid + i * 256]; s += xv[i]; }
    red[tid] = s; __syncthreads();
    for (int st = 128; st > 0; st >>= 1) { if (tid < st) red[tid] += red[tid + st]; __syncthreads(); }
    float mean = red[0] * (1.0f / (float)Dc);
    __syncthreads();
    float v = 0.f;
#pragma unroll
    for (int i = 0; i < 4; i++) { float t = xv[i] - mean; v += t * t; }
    red[tid] = v; __syncthreads();
    for (int st = 128; st > 0; st >>= 1) { if (tid < st) red[tid] += red[tid + st]; __syncthreads(); }
    float inv = 1.0f / (sqrtf(red[0] / (float)(Dc - 1)) + EPSc);
    float* o = out + (long)r * outStride;
#pragma unroll
    for (int i = 0; i < 4; i++) { int d = tid + i * 256; o[d] = sc[d] * ((xv[i] - mean) * inv) + sh[d]; }
}

// ---------------- single-pass causal softmax (row cached in smem) ----------
// One block per row. Row length <= Tc (8 KB) cached in shared memory:
// 1 global read + 1 global write; exp computed once per element (__expf).
__global__ __launch_bounds__(256)
void softmax_k(float* __restrict__ S)
{
    __shared__ float buf[Tc];
    __shared__ float red[9];
    long row = blockIdx.x;                 // = z*T + q
    int  q   = (int)(row % Tc);
    float* p = S + row * (long)Tc;
    int len  = q + 1;
    int tid  = threadIdx.x;
    int lane = tid & 31, warp = tid >> 5;

    // load row into smem, track max
    float mx = -1e30f;
    for (int k = tid; k < len; k += 256) { float v = p[k]; buf[k] = v; mx = fmaxf(mx, v); }
#pragma unroll
    for (int o = 16; o > 0; o >>= 1) mx = fmaxf(mx, __shfl_xor_sync(0xffffffffu, mx, o));
    if (lane == 0) red[warp] = mx;
    __syncthreads();
    if (tid < 32) {
        float m = (tid < 8) ? red[tid] : -1e30f;
#pragma unroll
        for (int o = 4; o > 0; o >>= 1) m = fmaxf(m, __shfl_xor_sync(0xffffffffu, m, o));
        if (tid == 0) red[8] = m;
    }
    __syncthreads();
    mx = red[8];

    // exp once, accumulate sum, keep exp in smem
    float sum = 0.f;
    for (int k = tid; k < len; k += 256) { float e = __expf(buf[k] - mx); buf[k] = e; sum += e; }
#pragma unroll
    for (int o = 16; o > 0; o >>= 1) sum += __shfl_xor_sync(0xffffffffu, sum, o);
    if (lane == 0) red[warp] = sum;
    __syncthreads();
    if (tid < 32) {
        float s2 = (tid < 8) ? red[tid] : 0.f;
#pragma unroll
        for (int o = 4; o > 0; o >>= 1) s2 += __shfl_xor_sync(0xffffffffu, s2, o);
        if (tid == 0) red[8] = s2;
    }
    __syncthreads();
    float inv = 1.0f / red[8];

    // write normalized probs + zero the remainder of the diagonal 128-block
    for (int k = tid; k < len; k += 256) p[k] = buf[k] * inv;
    int kzend = ((q >> 7) + 1) << 7; if (kzend > Tc) kzend = Tc;
    for (int k = len + tid; k < kzend; k += 256) p[k] = 0.f;
}

// ---------------- tf32 tensor-core batched GEMM (pipelined, permuted smem) ----
// C = scale*(A @ op(B)) [+bias][gelu][+resid]
// TRANSB: B is [N,K] row-major (C=A@B^T).  !TRANSB: B is [K,N] row-major.
#define BM 128
#define BN 128
#define BK 16

__device__ __forceinline__ int slotA_of(int lane) { return lane ^ ((lane >> 2) & 6); }
__device__ __forceinline__ int slotB_of(int lane) { return lane ^ ((lane & 16) >> 3); }

template<bool TRANSB>
__global__ __launch_bounds__(256, 2)
void gemm_tc(const float* __restrict__ A, int lda, long aO1, long aO2,
             const float* __restrict__ B, int ldb, long bO1, long bO2,
             float* __restrict__ C, int ldc, long cO1, long cO2,
             int M, int N, int K,
             const float* __restrict__ bias,
             const float* __restrict__ resid,
             float scale, int doGelu, int causalSkip, int causalKlim, int Hdiv)
{
    int m0 = blockIdx.y * BM;
    int n0 = blockIdx.x * BN;
    if (causalSkip && n0 > m0 + BM - 1) return;

    int z  = blockIdx.z;
    int zb = z / Hdiv, zh = z % Hdiv;
    A += (long)zb * aO1 + (long)zh * aO2;
    B += (long)zb * bO1 + (long)zh * bO2;
    C += (long)zb * cO1 + (long)zh * cO2;
    const float* R = resid ? (resid + (long)zb * cO1 + (long)zh * cO2) : (const float*)0;

    __shared__ float4 sA[2][512];
    __shared__ float2 sB[2][1024];

    int tid  = threadIdx.x;
    int lane = tid & 31, warp = tid >> 5;
    int wm = (warp & 1) * 64;     // 2 warps along M
    int wn = (warp >> 1) * 32;    // 4 warps along N
    int bA0 = wm >> 4;            // 0 or 4
    int nb0 = wn >> 3;            // 0,4,8,12
    int slA = slotA_of(lane);
    int slB = slotB_of(lane);

    float acc[4][4][4];
#pragma unroll
    for (int i = 0; i < 4; i++)
#pragma unroll
        for (int j = 0; j < 4; j++)
#pragma unroll
            for (int r = 0; r < 4; r++) acc[i][j][r] = 0.f;

    int Kend = K;
    if (causalKlim) { int lim = m0 + BM; if (lim < Kend) Kend = lim; }
    int nIter = Kend / BK;

    int am  = tid >> 1;           // A row 0..127
    int as  = tid & 1;            // A k-step 0/1
    int aB  = am >> 4;            // A block
    int arr = am & 15;
    int ag  = arr & 7;
    int aRegBase = arr >> 3;
    int aSlot[4];
#pragma unroll
    for (int c = 0; c < 4; c++) aSlot[c] = (ag * 4 + c) ^ (ag & 6);
    const float* Aptr = A + (long)(m0 + am) * lda + as * 8;
    bool aOK = (m0 + am) < M;

    const float* Bptr;
    int bn_nn = 0, bk_nn = 0;
    int bSlot[4];
    if (TRANSB) {
        int bg = arr & 7;
#pragma unroll
        for (int c = 0; c < 4; c++) bSlot[c] = (bg * 4 + c) ^ ((bg & 4) >> 1);
        Bptr = B + (long)(n0 + am) * ldb + as * 8;
    } else {
        bk_nn = tid >> 4;              // k within tile 0..15
        bn_nn = (tid & 15) * 8;        // col group
#pragma unroll
        for (int j = 0; j < 4; j++) bSlot[j] = 0;
        Bptr = B + (long)bk_nn * ldb + n0 + bn_nn;
    }
    bool bOK = TRANSB ? ((n0 + am) < N) : true;

    float4 pa0, pa1, pb0, pb1;
    // ---- prologue: load iter 0 ----
    {
        pa0 = make_float4(0,0,0,0); pa1 = pa0;
        if (aOK) { pa0 = *(const float4*)(Aptr); pa1 = *(const float4*)(Aptr + 4); }
        pb0 = make_float4(0,0,0,0); pb1 = pb0;
        if (TRANSB) {
            if (bOK) { pb0 = *(const float4*)(Bptr); pb1 = *(const float4*)(Bptr + 4); }
        } else {
            if (n0 + bn_nn     < N) pb0 = *(const float4*)(Bptr);
            if (n0 + bn_nn + 4 < N) pb1 = *(const float4*)(Bptr + 4);
        }
    }
    // ---- stage into buffer 0 ----
    {
        float va[8] = {pa0.x,pa0.y,pa0.z,pa0.w,pa1.x,pa1.y,pa1.z,pa1.w};
        float* baseA = (float*)&sA[0][(as * 8 + aB) * 32];
#pragma unroll
        for (int kk = 0; kk < 8; kk++)
            baseA[aSlot[kk & 3] * 4 + aRegBase + 2 * (kk >> 2)] = tf32r(va[kk]);
        if (TRANSB) {
            float vb[8] = {pb0.x,pb0.y,pb0.z,pb0.w,pb1.x,pb1.y,pb1.z,pb1.w};
            float2* baseB = &sB[0][(as * 16 + aB * 2 + (arr >> 3)) * 32];
#pragma unroll
            for (int kk = 0; kk < 4; kk++)
                baseB[bSlot[kk]] = make_float2(tf32r(vb[kk]), tf32r(vb[kk + 4]));
        } else {
            float vb[8] = {pb0.x,pb0.y,pb0.z,pb0.w,pb1.x,pb1.y,pb1.z,pb1.w};
            int s  = bk_nn >> 3, kk = bk_nn & 7, c = kk & 3, reg = kk >> 2;
            int nb = bn_nn >> 3;
            float* baseB = (float*)&sB[0][(s * 16 + nb) * 32];
#pragma unroll
            for (int j = 0; j < 8; j++) {
                int slot = (j * 4 + c) ^ ((j & 4) >> 1);
                baseB[slot * 2 + reg] = tf32r(vb[j]);
            }
        }
    }
    __syncthreads();

    for (int it = 0; it < nIter; it++) {
        int cur = it & 1;
        bool more = (it + 1) < nIter;
        // ---- prefetch next tile to registers ----
        if (more) {
            long ko = (long)(it + 1) * BK;
            pa0 = make_float4(0,0,0,0); pa1 = pa0;
            if (aOK) { pa0 = *(const float4*)(Aptr + ko); pa1 = *(const float4*)(Aptr + ko + 4); }
            pb0 = make_float4(0,0,0,0); pb1 = pb0;
            if (TRANSB) {
                if (bOK) { pb0 = *(const float4*)(Bptr + ko); pb1 = *(const float4*)(Bptr + ko + 4); }
            } else {
                const float* bp = Bptr + ko * ldb;
                if (n0 + bn_nn     < N) pb0 = *(const float4*)(bp);
                if (n0 + bn_nn + 4 < N) pb1 = *(const float4*)(bp + 4);
            }
        }

        // ---- mma on current buffer ----
#pragma unroll
        for (int s = 0; s < 2; s++) {
            float4 af[4]; float2 bf[4];
#pragma unroll
            for (int mi = 0; mi < 4; mi++) af[mi] = sA[cur][(s * 8 + bA0 + mi) * 32 + slA];
#pragma unroll
            for (int ni = 0; ni < 4; ni++) bf[ni] = sB[cur][(s * 16 + nb0 + ni) * 32 + slB];
#pragma unroll
            for (int mi = 0; mi < 4; mi++)
#pragma unroll
                for (int ni = 0; ni < 4; ni++)
                    mma_tf32(acc[mi][ni], (const uint32_t*)&af[mi], (const uint32_t*)&bf[ni]);
        }

        // ---- stage next tile into alternate buffer ----
        if (more) {
            int nxt = cur ^ 1;
            float va[8] = {pa0.x,pa0.y,pa0.z,pa0.w,pa1.x,pa1.y,pa1.z,pa1.w};
            float* baseA = (float*)&sA[nxt][(as * 8 + aB) * 32];
#pragma unroll
            for (int kk = 0; kk < 8; kk++)
                baseA[aSlot[kk & 3] * 4 + aRegBase + 2 * (kk >> 2)] = tf32r(va[kk]);
            float vb[8] = {pb0.x,pb0.y,pb0.z,pb0.w,pb1.x,pb1.y,pb1.z,pb1.w};
            if (TRANSB) {
                float2* baseB = &sB[nxt][(as * 16 + aB * 2 + (arr >> 3)) * 32];
#pragma unroll
                for (int kk = 0; kk < 4; kk++)
                    baseB[bSlot[kk]] = make_float2(tf32r(vb[kk]), tf32r(vb[kk + 4]));
            } else {
                int s  = bk_nn >> 3, kk = bk_nn & 7, c = kk & 3, reg = kk >> 2;
                int nb = bn_nn >> 3;
                float* baseB = (float*)&sB[nxt][(s * 16 + nb) * 32];
#pragma unroll
                for (int j = 0; j < 8; j++) {
                    int slot = (j * 4 + c) ^ ((j & 4) >> 1);
                    baseB[slot * 2 + reg] = tf32r(vb[j]);
                }
            }
        }
        __syncthreads();
    }

    // ---- epilogue ----
    int g = lane >> 2, c2 = (lane & 3) * 2;
#pragma unroll
    for (int mi = 0; mi < 4; mi++) {
#pragma unroll
        for (int ni = 0; ni < 4; ni++) {
            int r0 = m0 + wm + mi * 16 + g;
            int cn = n0 + wn + ni * 8 + c2;
#pragma unroll
            for (int e = 0; e < 4; e++) {
                int gm = r0 + (e >= 2 ? 8 : 0);
                int gn = cn + (e & 1);
                if (gm >= M || gn >= N) continue;
                float vv = acc[mi][ni][e] * scale;
                if (bias)   vv += bias[gn];
                if (doGelu) vv = gelu_f(vv);
                if (R)      vv += R[(long)gm * ldc + gn];
                C[(long)gm * ldc + gn] = vv;
            }
        }
    }
}

// ---------------- dedicated logits kernel (M=2, fp32, memory-bound) ----------
__global__ __launch_bounds__(256)
void logits_k(const float* __restrict__ fin,
              const float* __restrict__ Wemb,
              float* __restrict__ out)
{
    __shared__ float f0[Dc], f1[Dc];
    int tid = threadIdx.x;
    for (int i = tid; i < Dc; i += 256) { f0[i] = fin[i]; f1[i] = fin[Dc + i]; }
    __syncthreads();
    int warp = tid >> 5, lane = tid & 31;
    long v = (long)blockIdx.x * 8 + warp;
    if (v >= Vc) return;
    const float* w = Wemb + v * Dc;
    float d0 = 0.f, d1 = 0.f;
    for (int i = lane * 4; i < Dc; i += 128) {
        float4 wv = *(const float4*)(w + i);
        d0 += wv.x * f0[i] + wv.y * f0[i+1] + wv.z * f0[i+2] + wv.w * f0[i+3];
        d1 += wv.x * f1[i] + wv.y * f1[i+1] + wv.z * f1[i+2] + wv.w * f1[i+3];
    }
#pragma unroll
    for (int o = 16; o > 0; o >>= 1) {
        d0 += __shfl_xor_sync(0xffffffff, d0, o);
        d1 += __shfl_xor_sync(0xffffffff, d1, o);
    }
    if (lane == 0) { out[v] = d0; out[(long)Vc + v] = d1; }
}

// ---------------- host-side launch helpers ----------------
static inline void launch_nt(const float* A, int lda, long aO1, long aO2,
                             const float* B, int ldb, long bO1, long bO2,
                             float* C, int ldc, long cO1, long cO2,
                             int M, int N, int K,
                             const float* bias, const float* resid,
                             float scale, int gelu, int cskip, int cklim, int Hdiv, int batch)
{
    dim3 g((N + BN - 1) / BN, (M + BM - 1) / BM, batch);
    gemm_tc<true><<<g, 256>>>(A, lda, aO1, aO2, B, ldb, bO1, bO2, C, ldc, cO1, cO2,
                              M, N, K, bias, resid, scale, gelu, cskip, cklim, Hdiv);
}
static inline void launch_nn(const float* A, int lda, long aO1, long aO2,
                             const float* B, int ldb, long bO1, long bO2,
                             float* C, int ldc, long cO1, long cO2,
                             int M, int N, int K,
                             const float* bias, const float* resid,
                             float scale, int gelu, int cskip, int cklim, int Hdiv, int batch)
{
    dim3 g((N + BN - 1) / BN, (M + BM - 1) / BM, batch);
    gemm_tc<false><<<g, 256>>>(A, lda, aO1, aO2, B, ldb, bO1, bO2, C, ldc, cO1, cO2,
                               M, N, K, bias, resid, scale, gelu, cskip, cklim, Hdiv);
}

extern "C" void kernel_launch(void* const* d_in, const int* in_sizes, int n_in,
                              void* d_out, int out_size)
{
    const int*   x    = (const int*)  d_in[0];
    const float* Wemb = (const float*)d_in[1];
    const float* pos  = (const float*)d_in[2];
    const float* Wq   = (const float*)d_in[3];
    const float* Wk   = (const float*)d_in[4];
    const float* Wv   = (const float*)d_in[5];
    const float* Wo   = (const float*)d_in[6];
    const float* bo   = (const float*)d_in[7];
    const float* n1s  = (const float*)d_in[8];
    const float* n1b  = (const float*)d_in[9];
    const float* n2s  = (const float*)d_in[10];
    const float* n2b  = (const float*)d_in[11];
    const float* W1   = (const float*)d_in[12];
    const float* b1   = (const float*)d_in[13];
    const float* W2   = (const float*)d_in[14];
    const float* b2   = (const float*)d_in[15];
    const float* fs   = (const float*)d_in[16];
    const float* fb   = (const float*)d_in[17];
    float* out = (float*)d_out;

    float *h, *xn, *q, *k, *v, *ctx, *ff, *sc, *fin;
    cudaGetSymbolAddress((void**)&h,   g_h);
    cudaGetSymbolAddress((void**)&xn,  g_xn);
    cudaGetSymbolAddress((void**)&q,   g_q);
    cudaGetSymbolAddress((void**)&k,   g_k);
    cudaGetSymbolAddress((void**)&v,   g_v);
    cudaGetSymbolAddress((void**)&ctx, g_ctx);
    cudaGetSymbolAddress((void**)&ff,  g_ff);
    cudaGetSymbolAddress((void**)&sc,  g_sc);
    cudaGetSymbolAddress((void**)&fin, g_fin);

    const long TD  = (long)Tc * Dc;
    const long TT  = (long)Tc * Tc;
    const int  BH  = Bc * Hc;

    {
        long n = (long)BTc * Dc;
        embed_k<<<(unsigned)((n + 255) / 256), 256>>>(x, Wemb, pos, h);
    }

    for (int l = 0; l < Lc; l++) {
        const float* Wql = Wq + (long)l * Dc * Dc;
        const float* Wkl = Wk + (long)l * Dc * Dc;
        const float* Wvl = Wv + (long)l * Dc * Dc;
        const float* Wol = Wo + (long)l * Dc * Dc;
        const float* bol = bo + (long)l * Dc;
        const float* W1l = W1 + (long)l * DFFc * Dc;
        const float* b1l = b1 + (long)l * DFFc;
        const float* W2l = W2 + (long)l * Dc * DFFc;
        const float* b2l = b2 + (long)l * Dc;

        // LN1
        ln_k<<<BTc, 256>>>(h, Dc, xn, Dc, n1s + (long)l * Dc, n1b + (long)l * Dc);

        // Q,K,V = xn @ W^T
        launch_nt(xn, Dc, 0, 0, Wql, Dc, 0, 0, q, Dc, 0, 0, BTc, Dc, Dc, 0, 0, 1.f, 0, 0, 0, 1, 1);
        launch_nt(xn, Dc, 0, 0, Wkl, Dc, 0, 0, k, Dc, 0, 0, BTc, Dc, Dc, 0, 0, 1.f, 0, 0, 0, 1, 1);
        launch_nt(xn, Dc, 0, 0, Wvl, Dc, 0, 0, v, Dc, 0, 0, BTc, Dc, Dc, 0, 0, 1.f, 0, 0, 0, 1, 1);

        // scores = (Q.K)/8 with causal block skip, batched over z=(b,h)
        launch_nt(q, Dc, TD, HDc, k, Dc, TD, HDc,
                  sc, Tc, (long)Hc * TT, TT,
                  Tc, Tc, HDc, 0, 0, 1.0f / 8.0f, 0, /*cskip=*/1, 0, Hc, BH);

        // causal softmax in-place (single-pass, smem row cache)
        softmax_k<<<(unsigned)(BH * Tc), 256>>>(sc);

        // ctx = P @ V  (NN, causal K limit)
        launch_nn(sc, Tc, (long)Hc * TT, TT, v, Dc, TD, HDc,
                  ctx, Dc, TD, HDc,
                  Tc, HDc, Tc, 0, 0, 1.f, 0, 0, /*cklim=*/1, Hc, BH);

        // h = h + ctx @ Wo^T + bo
        launch_nt(ctx, Dc, 0, 0, Wol, Dc, 0, 0, h, Dc, 0, 0, BTc, Dc, Dc, bol, h, 1.f, 0, 0, 0, 1, 1);

        // LN2
        ln_k<<<BTc, 256>>>(h, Dc, xn, Dc, n2s + (long)l * Dc, n2b + (long)l * Dc);

        // ff = gelu(xn @ W1^T + b1)
        launch_nt(xn, Dc, 0, 0, W1l, Dc, 0, 0, ff, DFFc, 0, 0, BTc, DFFc, Dc, b1l, 0, 1.f, 1, 0, 0, 1, 1);

        // h = h + ff @ W2^T + b2
        launch_nt(ff, DFFc, 0, 0, W2l, DFFc, 0, 0, h, Dc, 0, 0, BTc, Dc, DFFc, b2l, h, 1.f, 0, 0, 0, 1, 1);
    }

    // final LN on the 2 last-token rows only
    ln_k<<<Bc, 256>>>(h + (long)(Tc - 1) * Dc, TD, fin, Dc, fs, fb);

    // logits (fp32, memory-bound dedicated kernel)
    logits_k<<<(Vc + 7) / 8, 256>>>(fin, Wemb, out);
}